// round 1
// baseline (speedup 1.0000x reference)
#include <cuda_runtime.h>
#include <math.h>

// Problem constants
#define B_ 256
#define S_ 14
#define F_ 1024
#define H_ 1024
#define C_ 2513
#define SB 3584          // S_*B_
#define BH 262144        // B_*H_
#define G4 4096          // 4*H_

// ---------------- scratch (device globals; no allocation allowed) ------------
__device__ float g_xT  [SB * F_];      // x transposed to [S,B,F]
__device__ float g_xg_r[SB * G4];      // input-gate preactivations (rolling)
__device__ float g_xg_u[SB * G4];      // input-gate preactivations (unrolling)
__device__ float g_hs  [SB * H_];      // rolling h per step  [S,B,H]
__device__ float g_cs  [SB * H_];      // rolling c per step
__device__ float g_hu  [2 * SB * H_];  // unroll h ping-pong
__device__ float g_cu  [SB * H_];      // unroll c (in-place safe)
__device__ float g_hn  [SB * H_];      // final hidden per t  [S,B,H]

__device__ __forceinline__ float sigf(float x) { return 1.0f / (1.0f + expf(-x)); }

// ---------------- transpose [B,S,F] -> [S,B,F] -------------------------------
__global__ void k_transpose(const float4* __restrict__ in, float4* __restrict__ out) {
    const int F4 = F_ / 4;
    int idx = blockIdx.x * blockDim.x + threadIdx.x;
    if (idx >= SB * F4) return;
    int f4  = idx % F4;
    int row = idx / F4;          // row = s*B + b
    int b = row % B_;
    int s = row / B_;
    out[idx] = in[(size_t)(b * S_ + s) * F4 + f4];
}

// ---------------- generic SGEMM: C[M,N] = A[M,K] @ W[N,K]^T + bias -----------
// K fixed = 1024.  M must be multiple of 128.  N-edge predicated.
// permuteBS: output row m=(s*B+b) written to row (b*S+s).
__global__ void __launch_bounds__(256) k_sgemm(
    const float* __restrict__ A, const float* __restrict__ W,
    float* __restrict__ Cd, int M, int N,
    const float* __restrict__ bias0, const float* __restrict__ bias1,
    int permuteBS)
{
    (void)M;
    __shared__ float As[16][132];
    __shared__ float Ws[16][132];
    const int tid = threadIdx.x;
    const int tx = tid & 15, ty = tid >> 4;
    const int m0 = blockIdx.y * 128;
    const int n0 = blockIdx.x * 128;
    const int lr = tid >> 2;          // 0..63
    const int lk = (tid & 3) << 2;    // 0,4,8,12

    float acc[8][8];
#pragma unroll
    for (int i = 0; i < 8; i++)
#pragma unroll
        for (int j = 0; j < 8; j++) acc[i][j] = 0.f;

    for (int kt = 0; kt < 1024; kt += 16) {
#pragma unroll
        for (int r = 0; r < 2; r++) {
            int row = lr + r * 64;
            float4 v = *(const float4*)&A[(size_t)(m0 + row) * 1024 + kt + lk];
            As[lk + 0][row] = v.x; As[lk + 1][row] = v.y;
            As[lk + 2][row] = v.z; As[lk + 3][row] = v.w;
            int wrow = n0 + row;
            float4 wv = make_float4(0.f, 0.f, 0.f, 0.f);
            if (wrow < N) wv = *(const float4*)&W[(size_t)wrow * 1024 + kt + lk];
            Ws[lk + 0][row] = wv.x; Ws[lk + 1][row] = wv.y;
            Ws[lk + 2][row] = wv.z; Ws[lk + 3][row] = wv.w;
        }
        __syncthreads();
#pragma unroll
        for (int k = 0; k < 16; k++) {
            float a[8], w[8];
#pragma unroll
            for (int i = 0; i < 8; i++) a[i] = As[k][ty * 8 + i];
#pragma unroll
            for (int j = 0; j < 8; j++) w[j] = Ws[k][tx * 8 + j];
#pragma unroll
            for (int i = 0; i < 8; i++)
#pragma unroll
                for (int j = 0; j < 8; j++) acc[i][j] = fmaf(a[i], w[j], acc[i][j]);
        }
        __syncthreads();
    }

#pragma unroll
    for (int i = 0; i < 8; i++) {
        int m = m0 + ty * 8 + i;
        int orow = m;
        if (permuteBS) { int s = m / B_, b = m % B_; orow = b * S_ + s; }
#pragma unroll
        for (int j = 0; j < 8; j++) {
            int n = n0 + tx * 8 + j;
            if (n < N) {
                float v = acc[i][j];
                if (bias0) v += bias0[n];
                if (bias1) v += bias1[n];
                Cd[(size_t)orow * N + n] = v;
            }
        }
    }
}

// ---------------- fused LSTM step: gates GEMM + activation -------------------
// Virtual column n' in [0,4096): unit u = n'>>2, gate g = n'&3,
// weight row = g*1024 + u.  Each thread's 8 consecutive n' = 2 units x 4 gates,
// so the gate update happens entirely in registers in the epilogue.
// acc = Hin[M,1024] @ Whh'[n',k];  pre = acc + xg;  h2,c2 -> Hout,Cout.
// zeroInit: skip GEMM (h=0) and c=0 (rolling t=0).
// final_t: rows with (m>>8)==final_t additionally written to Hfin.
template <int BM>
__global__ void __launch_bounds__(256) k_lstm_step(
    const float* __restrict__ Hin, const float* __restrict__ Whh,
    const float* __restrict__ xg, const float* __restrict__ Cin,
    float* __restrict__ Hout, float* __restrict__ Cout,
    float* __restrict__ Hfin, int final_t, int zeroInit)
{
    constexpr int TM = BM / 16;           // 8 (BM=128) or 4 (BM=64)
    __shared__ float As[16][BM + 4];
    __shared__ float Ws[16][132];
    const int tid = threadIdx.x;
    const int tx = tid & 15, ty = tid >> 4;
    const int m0 = blockIdx.y * BM;
    const int n0 = blockIdx.x * 128;      // n' base

    float acc[TM][8];
#pragma unroll
    for (int i = 0; i < TM; i++)
#pragma unroll
        for (int j = 0; j < 8; j++) acc[i][j] = 0.f;

    if (!zeroInit) {
        const int lr = tid >> 2;
        const int lk = (tid & 3) << 2;
        for (int kt = 0; kt < 1024; kt += 16) {
#pragma unroll
            for (int r = 0; r < BM / 64; r++) {
                int row = lr + r * 64;
                float4 v = *(const float4*)&Hin[(size_t)(m0 + row) * 1024 + kt + lk];
                As[lk + 0][row] = v.x; As[lk + 1][row] = v.y;
                As[lk + 2][row] = v.z; As[lk + 3][row] = v.w;
            }
#pragma unroll
            for (int r = 0; r < 2; r++) {
                int wr = lr + r * 64;
                int np = n0 + wr;
                int wrow = ((np & 3) << 10) + (np >> 2);
                float4 v = *(const float4*)&Whh[(size_t)wrow * 1024 + kt + lk];
                Ws[lk + 0][wr] = v.x; Ws[lk + 1][wr] = v.y;
                Ws[lk + 2][wr] = v.z; Ws[lk + 3][wr] = v.w;
            }
            __syncthreads();
#pragma unroll
            for (int k = 0; k < 16; k++) {
                float a[TM], w[8];
#pragma unroll
                for (int i = 0; i < TM; i++) a[i] = As[k][ty * TM + i];
#pragma unroll
                for (int j = 0; j < 8; j++) w[j] = Ws[k][tx * 8 + j];
#pragma unroll
                for (int i = 0; i < TM; i++)
#pragma unroll
                    for (int j = 0; j < 8; j++) acc[i][j] = fmaf(a[i], w[j], acc[i][j]);
            }
            __syncthreads();
        }
    }

    const int u0 = (n0 + tx * 8) >> 2;
#pragma unroll
    for (int i = 0; i < TM; i++) {
        int m = m0 + ty * TM + i;
        const float* xr = xg + (size_t)m * G4;
#pragma unroll
        for (int uu = 0; uu < 2; uu++) {
            int u = u0 + uu;
            float pi = acc[i][uu * 4 + 0] + xr[u];
            float pf = acc[i][uu * 4 + 1] + xr[1024 + u];
            float pg = acc[i][uu * 4 + 2] + xr[2048 + u];
            float po = acc[i][uu * 4 + 3] + xr[3072 + u];
            float c  = zeroInit ? 0.f : Cin[(size_t)m * 1024 + u];
            float c2 = sigf(pf) * c + sigf(pi) * tanhf(pg);
            float h2 = sigf(po) * tanhf(c2);
            Hout[(size_t)m * 1024 + u] = h2;
            Cout[(size_t)m * 1024 + u] = c2;
            if ((m >> 8) == final_t) Hfin[(size_t)m * 1024 + u] = h2;
        }
    }
}

// ---------------- host orchestration ----------------------------------------
extern "C" void kernel_launch(void* const* d_in, const int* in_sizes, int n_in,
                              void* d_out, int out_size) {
    (void)in_sizes; (void)n_in; (void)out_size;
    const float* inp   = (const float*)d_in[0];
    const float* Wih_r = (const float*)d_in[1];
    const float* Whh_r = (const float*)d_in[2];
    const float* bih_r = (const float*)d_in[3];
    const float* bhh_r = (const float*)d_in[4];
    const float* Wih_u = (const float*)d_in[5];
    const float* Whh_u = (const float*)d_in[6];
    const float* bih_u = (const float*)d_in[7];
    const float* bhh_u = (const float*)d_in[8];
    const float* Wc    = (const float*)d_in[9];
    const float* bc    = (const float*)d_in[10];
    float* out = (float*)d_out;

    float *xT, *xg_r, *xg_u, *hs, *cs, *hu, *cu, *hn;
    cudaGetSymbolAddress((void**)&xT,   g_xT);
    cudaGetSymbolAddress((void**)&xg_r, g_xg_r);
    cudaGetSymbolAddress((void**)&xg_u, g_xg_u);
    cudaGetSymbolAddress((void**)&hs,   g_hs);
    cudaGetSymbolAddress((void**)&cs,   g_cs);
    cudaGetSymbolAddress((void**)&hu,   g_hu);
    cudaGetSymbolAddress((void**)&cu,   g_cu);
    cudaGetSymbolAddress((void**)&hn,   g_hn);
    float* hu0 = hu;
    float* hu1 = hu + (size_t)SB * H_;

    // 1) transpose inputs to [S,B,F]
    {
        int total = SB * (F_ / 4);
        k_transpose<<<(total + 255) / 256, 256>>>((const float4*)inp, (float4*)xT);
    }

    // 2) input projections xg = xT @ Wih^T + bih + bhh
    {
        dim3 g((G4 + 127) / 128, SB / 128);
        k_sgemm<<<g, 256>>>(xT, Wih_r, xg_r, SB, G4, bih_r, bhh_r, 0);
        k_sgemm<<<g, 256>>>(xT, Wih_u, xg_u, SB, G4, bih_u, bhh_u, 0);
    }

    // 3) rolling LSTM: 14 sequential fused steps, M = 256
    for (int t = 0; t < S_; t++) {
        dim3 g(G4 / 128, B_ / 64);
        const float* hin = (t == 0) ? nullptr : hs + (size_t)(t - 1) * BH;
        const float* cin = (t == 0) ? nullptr : cs + (size_t)(t - 1) * BH;
        k_lstm_step<64><<<g, 256>>>(hin, Whh_r,
                                    xg_r + (size_t)t * B_ * G4, cin,
                                    hs + (size_t)t * BH, cs + (size_t)t * BH,
                                    hn, -1, (t == 0) ? 1 : 0);
    }

    // 4) init unroll state from rolling trajectory
    cudaMemcpyAsync(hu0, hs, sizeof(float) * (size_t)SB * H_, cudaMemcpyDeviceToDevice, 0);
    cudaMemcpyAsync(cu,  cs, sizeof(float) * (size_t)SB * H_, cudaMemcpyDeviceToDevice, 0);

    // 5) unrolling LSTM: 15 batched sequential steps; instance t active for j<=S-t.
    //    Active instances are the contiguous prefix t in [0, nact).
    for (int j = 0; j <= S_; j++) {
        int nact = (15 - j < 14) ? (15 - j) : 14;
        int M = nact * B_;
        const float* hin = (j & 1) ? hu1 : hu0;
        float*       ho  = (j & 1) ? hu0 : hu1;
        int final_t = S_ - j;   // instance finishing this step (j=0 -> 14: none)
        if (M >= 1024) {
            dim3 g(G4 / 128, M / 128);
            k_lstm_step<128><<<g, 256>>>(hin, Whh_u, xg_u, cu, ho, cu, hn, final_t, 0);
        } else {
            dim3 g(G4 / 128, M / 64);
            k_lstm_step<64><<<g, 256>>>(hin, Whh_u, xg_u, cu, ho, cu, hn, final_t, 0);
        }
    }

    // 6) classifier: y[b,s,:] = hn[s*B+b,:] @ Wc^T + bc  (permuted output rows)
    {
        dim3 g((C_ + 127) / 128, SB / 128);
        k_sgemm<<<g, 256>>>(hn, Wc, out, SB, C_, bc, nullptr, 1);
    }
}

// round 3
// speedup vs baseline: 2.2715x; 2.2715x over previous
#include <cuda_runtime.h>
#include <math.h>
#include <stdint.h>

// ---------------- problem constants ----------------
#define B_ 256
#define S_ 14
#define C_ 2513
#define SB 3584          // S_*B_
#define BH 262144        // B_*H_
#define G4 4096          // 4*H_

// ---------------- mma.sync GEMM config ----------------
#define ASTRIDE 36                     // padded SMEM row stride (floats)
#define STAGEF  (128 * ASTRIDE)        // floats per operand per stage = 4608
#define SMEM_FLOATS (4 * STAGEF + 128) // 2 stages x (A+B) + bias row
#define SMEM_BYTES  (SMEM_FLOATS * 4)  // 74240

// ---------------- scratch (device globals) ----------------
__device__ float g_xT  [SB * 1024];
__device__ float g_xg_r[(size_t)SB * G4];   // gate-interleaved [m][u*4+g]
__device__ float g_xg_u[(size_t)SB * G4];
__device__ float g_hs  [SB * 1024];
__device__ float g_cs  [SB * 1024];
__device__ float g_hu  [2 * SB * 1024];
__device__ float g_cu  [SB * 1024];
__device__ float g_hn  [SB * 1024];

__device__ __forceinline__ float sigf(float x) { return 1.0f / (1.0f + expf(-x)); }

// ---------------- low-level helpers ----------------
__device__ __forceinline__ uint32_t f2tf(float x) {
    uint32_t r; asm("cvt.rna.tf32.f32 %0, %1;" : "=r"(r) : "f"(x)); return r;
}
__device__ __forceinline__ uint32_t smaddr(const void* p) {
    uint32_t a;
    asm("{ .reg .u64 t; cvta.to.shared.u64 t, %1; cvt.u32.u64 %0, t; }" : "=r"(a) : "l"(p));
    return a;
}
__device__ __forceinline__ void cp16(uint32_t d, const void* s) {
    asm volatile("cp.async.cg.shared.global [%0], [%1], 16;" :: "r"(d), "l"(s));
}
__device__ __forceinline__ void cp16z(uint32_t d, const void* s, int sz) {
    asm volatile("cp.async.cg.shared.global [%0], [%1], 16, %2;" :: "r"(d), "l"(s), "r"(sz));
}
__device__ __forceinline__ void cpcommit() { asm volatile("cp.async.commit_group;"); }
__device__ __forceinline__ void cpwait0()  { asm volatile("cp.async.wait_group 0;"); }
__device__ __forceinline__ void cpwait1()  { asm volatile("cp.async.wait_group 1;"); }

__device__ __forceinline__ void mma8(float* d, const uint32_t* a, const uint32_t* b) {
    asm volatile(
        "mma.sync.aligned.m16n8k8.row.col.f32.tf32.tf32.f32 "
        "{%0,%1,%2,%3},{%4,%5,%6,%7},{%8,%9},{%0,%1,%2,%3};"
        : "+f"(d[0]), "+f"(d[1]), "+f"(d[2]), "+f"(d[3])
        : "r"(a[0]), "r"(a[1]), "r"(a[2]), "r"(a[3]), "r"(b[0]), "r"(b[1]));
}

// ---------------- stage issue: global -> SMEM via cp.async ----------------
// A tile: rows m0..m0+127, k = kt*32..+31.  B tile: 128 "virtual" output cols.
// GREMAP: vcol np -> weight row ((np&3)*1024 + (np>>2)) (gate interleave).
// Rows with wr >= Nb are zero-filled.
template <int GREMAP>
__device__ __forceinline__ void stage_issue(
    float* sm, int s, const float* __restrict__ A, const float* __restrict__ W,
    int m0, int n0, int kt, int Nb, int tid)
{
    float* dA = sm + s * 2 * STAGEF;
    float* dB = dA + STAGEF;
    const float* Ap = A + (size_t)m0 * 1024 + kt * 32;
    const float* Wp = W + kt * 32;
#pragma unroll
    for (int i = 0; i < 4; i++) {
        int idx = tid + (i << 8);
        int row = idx >> 3, c4 = idx & 7;
        cp16(smaddr(dA + row * ASTRIDE + c4 * 4), Ap + (size_t)row * 1024 + c4 * 4);
        int np = n0 + row;
        int wr = GREMAP ? (((np & 3) << 10) | (np >> 2)) : np;
        int ok = (wr < Nb);
        cp16z(smaddr(dB + row * ASTRIDE + c4 * 4),
              Wp + (size_t)(ok ? wr : 0) * 1024 + c4 * 4, ok ? 16 : 0);
    }
    cpcommit();
}

// ---------------- stage compute: 4 k-steps of 16 MMAs per warp ----------------
__device__ __forceinline__ void stage_compute(
    const float* sm, int s, int wm, int wn, int g, int tig, float acc[4][4][4])
{
    const float* bA = sm + s * 2 * STAGEF + (wm * 64) * ASTRIDE;
    const float* bB = sm + s * 2 * STAGEF + STAGEF + (wn * 32) * ASTRIDE;
#pragma unroll
    for (int ks = 0; ks < 4; ks++) {
        const int k = ks * 8 + tig;
        uint32_t af[4][4], bf[4][2];
#pragma unroll
        for (int mi = 0; mi < 4; mi++) {
            const float* p = bA + (mi * 16 + g) * ASTRIDE + k;
            af[mi][0] = f2tf(p[0]);
            af[mi][1] = f2tf(p[8 * ASTRIDE]);
            af[mi][2] = f2tf(p[4]);
            af[mi][3] = f2tf(p[8 * ASTRIDE + 4]);
        }
#pragma unroll
        for (int ni = 0; ni < 4; ni++) {
            const float* p = bB + (ni * 8 + g) * ASTRIDE + k;
            bf[ni][0] = f2tf(p[0]);
            bf[ni][1] = f2tf(p[4]);
        }
#pragma unroll
        for (int mi = 0; mi < 4; mi++)
#pragma unroll
            for (int ni = 0; ni < 4; ni++) mma8(acc[mi][ni], af[mi], bf[ni]);
    }
}

// ---------------- full K=1024 mainloop (2-stage pipeline) ----------------
template <int GREMAP>
__device__ __forceinline__ void run_mainloop(
    float* sm, const float* __restrict__ A, const float* __restrict__ W,
    int m0, int n0, int Nb, float acc[4][4][4],
    int tid, int wm, int wn, int g, int tig)
{
    stage_issue<GREMAP>(sm, 0, A, W, m0, n0, 0, Nb, tid);
    stage_issue<GREMAP>(sm, 1, A, W, m0, n0, 1, Nb, tid);
#pragma unroll 1
    for (int kt = 0; kt < 32; kt++) {
        int s = kt & 1;
        if (kt + 1 < 32) cpwait1(); else cpwait0();
        __syncthreads();
        stage_compute(sm, s, wm, wn, g, tig, acc);
        __syncthreads();
        if (kt + 2 < 32) stage_issue<GREMAP>(sm, s, A, W, m0, n0, kt + 2, Nb, tid);
    }
}

// ---------------- fused tensor-core LSTM step ----------------
// D[m][vcol] = Hin @ Whh'(vcol)^T; vcol = u*4+g; epilogue pairs lanes via
// shfl_xor(1) so each lane owns all 4 gates of one (row, unit).
__global__ void __launch_bounds__(256) k_mma_lstm(
    const float* __restrict__ Hin, const float* __restrict__ Whh,
    const float* __restrict__ xg, const float* __restrict__ Cin,
    float* __restrict__ Hout, float* __restrict__ Cout,
    float* __restrict__ Hfin, int final_t)
{
    extern __shared__ float sm[];
    const int tid = threadIdx.x, lane = tid & 31, wid = tid >> 5;
    const int wm = wid & 1, wn = wid >> 1, g = lane >> 2, tig = lane & 3;
    const int m0 = blockIdx.y * 128, n0 = blockIdx.x * 128;

    float acc[4][4][4];
#pragma unroll
    for (int a = 0; a < 4; a++)
#pragma unroll
        for (int b = 0; b < 4; b++)
#pragma unroll
            for (int c = 0; c < 4; c++) acc[a][b][c] = 0.f;

    run_mainloop<1>(sm, Hin, Whh, m0, n0, 0x7fffffff, acc, tid, wm, wn, g, tig);

#pragma unroll
    for (int mi = 0; mi < 4; mi++) {
        const int R0 = m0 + wm * 64 + mi * 16;
#pragma unroll
        for (int ni = 0; ni < 4; ni++) {
            const int V0 = n0 + wn * 32 + ni * 8;
            float c0 = acc[mi][ni][0], c1 = acc[mi][ni][1];
            float c2 = acc[mi][ni][2], c3 = acc[mi][ni][3];
            int p = tig & 1;
            float x = p ? c0 : c2, y = p ? c1 : c3;
            float sx = __shfl_xor_sync(0xffffffffu, x, 1);
            float sy = __shfl_xor_sync(0xffffffffu, y, 1);
            float pi, pf, pg, po; int row;
            if (!p) { pi = c0; pf = c1; pg = sx; po = sy; row = R0 + g; }
            else    { pi = sx; pf = sy; pg = c2; po = c3; row = R0 + g + 8; }
            int u = (V0 >> 2) + (tig >> 1);
            float4 xv = *(const float4*)(xg + (size_t)row * G4 + u * 4);
            float ci = Cin[(size_t)row * 1024 + u];
            float cn = sigf(pf + xv.y) * ci + sigf(pi + xv.x) * tanhf(pg + xv.z);
            float hv = sigf(po + xv.w) * tanhf(cn);
            Hout[(size_t)row * 1024 + u] = hv;
            Cout[(size_t)row * 1024 + u] = cn;
            if ((row >> 8) == final_t) Hfin[(size_t)row * 1024 + u] = hv;
        }
    }
}

// ---------------- tensor-core linear ----------------
// MODE 1: projection -> gate-interleaved output [m][u*4+g], bias b0[wr]+b1[wr]
// MODE 0: classifier -> rows permuted (b*S+s), N-edge predicated, bias b0[n]
template <int MODE>
__global__ void __launch_bounds__(256) k_mma_lin(
    const float* __restrict__ A, const float* __restrict__ W,
    float* __restrict__ Out, const float* __restrict__ b0,
    const float* __restrict__ b1, int N)
{
    extern __shared__ float sm[];
    float* biasS = sm + 4 * STAGEF;
    const int tid = threadIdx.x, lane = tid & 31, wid = tid >> 5;
    const int wm = wid & 1, wn = wid >> 1, g = lane >> 2, tig = lane & 3;
    const int m0 = blockIdx.y * 128, n0 = blockIdx.x * 128;

    if (tid < 128) {
        int np = n0 + tid;
        float bv = 0.f;
        if (MODE == 1) { int wr = ((np & 3) << 10) | (np >> 2); bv = b0[wr] + b1[wr]; }
        else if (np < N) bv = b0[np];
        biasS[tid] = bv;
    }

    float acc[4][4][4];
#pragma unroll
    for (int a = 0; a < 4; a++)
#pragma unroll
        for (int b = 0; b < 4; b++)
#pragma unroll
            for (int c = 0; c < 4; c++) acc[a][b][c] = 0.f;

    run_mainloop<MODE>(sm, A, W, m0, n0, MODE ? 0x7fffffff : N, acc, tid, wm, wn, g, tig);

#pragma unroll
    for (int mi = 0; mi < 4; mi++) {
        const int R0 = m0 + wm * 64 + mi * 16;
#pragma unroll
        for (int ni = 0; ni < 4; ni++) {
            const int V0 = n0 + wn * 32 + ni * 8;
            const int v = V0 + 2 * tig;
            const float bA0 = biasS[v - n0], bA1 = biasS[v - n0 + 1];
            const int r1 = R0 + g, r2 = R0 + g + 8;
            if (MODE == 1) {
                float2 s1 = make_float2(acc[mi][ni][0] + bA0, acc[mi][ni][1] + bA1);
                float2 s2 = make_float2(acc[mi][ni][2] + bA0, acc[mi][ni][3] + bA1);
                *(float2*)(Out + (size_t)r1 * G4 + v) = s1;
                *(float2*)(Out + (size_t)r2 * G4 + v) = s2;
            } else {
                int or1 = (r1 & 255) * S_ + (r1 >> 8);
                int or2 = (r2 & 255) * S_ + (r2 >> 8);
                if (v < N) {
                    Out[(size_t)or1 * N + v] = acc[mi][ni][0] + bA0;
                    Out[(size_t)or2 * N + v] = acc[mi][ni][2] + bA0;
                }
                if (v + 1 < N) {
                    Out[(size_t)or1 * N + v + 1] = acc[mi][ni][1] + bA1;
                    Out[(size_t)or2 * N + v + 1] = acc[mi][ni][3] + bA1;
                }
            }
        }
    }
}

// ---------------- transpose [B,S,F] -> [S,B,F] ----------------
__global__ void k_transpose(const float4* __restrict__ in, float4* __restrict__ out) {
    const int F4 = 1024 / 4;
    int idx = blockIdx.x * blockDim.x + threadIdx.x;
    if (idx >= SB * F4) return;
    int f4  = idx % F4;
    int row = idx / F4;
    int b = row % B_;
    int s = row / B_;
    out[idx] = in[(size_t)(b * S_ + s) * F4 + f4];
}

// ---------------- FFMA rolling LSTM step (M=256, latency-bound) ----------------
// xg is gate-interleaved [m][u*4+g].
__global__ void __launch_bounds__(256) k_lstm_step(
    const float* __restrict__ Hin, const float* __restrict__ Whh,
    const float* __restrict__ xg, const float* __restrict__ Cin,
    float* __restrict__ Hout, float* __restrict__ Cout, int zeroInit)
{
    constexpr int BM = 64, TM = 4;
    __shared__ float As[16][BM + 4];
    __shared__ float Ws[16][132];
    const int tid = threadIdx.x;
    const int tx = tid & 15, ty = tid >> 4;
    const int m0 = blockIdx.y * BM;
    const int n0 = blockIdx.x * 128;

    float acc[TM][8];
#pragma unroll
    for (int i = 0; i < TM; i++)
#pragma unroll
        for (int j = 0; j < 8; j++) acc[i][j] = 0.f;

    if (!zeroInit) {
        const int lr = tid >> 2;
        const int lk = (tid & 3) << 2;
        for (int kt = 0; kt < 1024; kt += 16) {
            {
                int row = lr;
                float4 v = *(const float4*)&Hin[(size_t)(m0 + row) * 1024 + kt + lk];
                As[lk + 0][row] = v.x; As[lk + 1][row] = v.y;
                As[lk + 2][row] = v.z; As[lk + 3][row] = v.w;
            }
#pragma unroll
            for (int r = 0; r < 2; r++) {
                int wr = lr + r * 64;
                int np = n0 + wr;
                int wrow = ((np & 3) << 10) + (np >> 2);
                float4 v = *(const float4*)&Whh[(size_t)wrow * 1024 + kt + lk];
                Ws[lk + 0][wr] = v.x; Ws[lk + 1][wr] = v.y;
                Ws[lk + 2][wr] = v.z; Ws[lk + 3][wr] = v.w;
            }
            __syncthreads();
#pragma unroll
            for (int k = 0; k < 16; k++) {
                float a[TM], w[8];
#pragma unroll
                for (int i = 0; i < TM; i++) a[i] = As[k][ty * TM + i];
#pragma unroll
                for (int j = 0; j < 8; j++) w[j] = Ws[k][tx * 8 + j];
#pragma unroll
                for (int i = 0; i < TM; i++)
#pragma unroll
                    for (int j = 0; j < 8; j++) acc[i][j] = fmaf(a[i], w[j], acc[i][j]);
            }
            __syncthreads();
        }
    }

    const int u0 = (n0 + tx * 8) >> 2;
#pragma unroll
    for (int i = 0; i < TM; i++) {
        int m = m0 + ty * TM + i;
        const float* xr = xg + (size_t)m * G4;
#pragma unroll
        for (int uu = 0; uu < 2; uu++) {
            int u = u0 + uu;
            float4 xv = *(const float4*)&xr[(size_t)u * 4];
            float pi = acc[i][uu * 4 + 0] + xv.x;
            float pf = acc[i][uu * 4 + 1] + xv.y;
            float pg = acc[i][uu * 4 + 2] + xv.z;
            float po = acc[i][uu * 4 + 3] + xv.w;
            float c  = zeroInit ? 0.f : Cin[(size_t)m * 1024 + u];
            float c2 = sigf(pf) * c + sigf(pi) * tanhf(pg);
            float h2 = sigf(po) * tanhf(c2);
            Hout[(size_t)m * 1024 + u] = h2;
            Cout[(size_t)m * 1024 + u] = c2;
        }
    }
}

// ---------------- host orchestration ----------------
extern "C" void kernel_launch(void* const* d_in, const int* in_sizes, int n_in,
                              void* d_out, int out_size) {
    (void)in_sizes; (void)n_in; (void)out_size;
    const float* inp   = (const float*)d_in[0];
    const float* Wih_r = (const float*)d_in[1];
    const float* Whh_r = (const float*)d_in[2];
    const float* bih_r = (const float*)d_in[3];
    const float* bhh_r = (const float*)d_in[4];
    const float* Wih_u = (const float*)d_in[5];
    const float* Whh_u = (const float*)d_in[6];
    const float* bih_u = (const float*)d_in[7];
    const float* bhh_u = (const float*)d_in[8];
    const float* Wc    = (const float*)d_in[9];
    const float* bc    = (const float*)d_in[10];
    float* out = (float*)d_out;

    float *xT, *xg_r, *xg_u, *hs, *cs, *hu, *cu, *hn;
    cudaGetSymbolAddress((void**)&xT,   g_xT);
    cudaGetSymbolAddress((void**)&xg_r, g_xg_r);
    cudaGetSymbolAddress((void**)&xg_u, g_xg_u);
    cudaGetSymbolAddress((void**)&hs,   g_hs);
    cudaGetSymbolAddress((void**)&cs,   g_cs);
    cudaGetSymbolAddress((void**)&hu,   g_hu);
    cudaGetSymbolAddress((void**)&cu,   g_cu);
    cudaGetSymbolAddress((void**)&hn,   g_hn);
    float* hu0 = hu;
    float* hu1 = hu + (size_t)SB * 1024;

    cudaFuncSetAttribute(k_mma_lstm,   cudaFuncAttributeMaxDynamicSharedMemorySize, SMEM_BYTES);
    cudaFuncSetAttribute(k_mma_lin<1>, cudaFuncAttributeMaxDynamicSharedMemorySize, SMEM_BYTES);
    cudaFuncSetAttribute(k_mma_lin<0>, cudaFuncAttributeMaxDynamicSharedMemorySize, SMEM_BYTES);

    // 1) transpose inputs to [S,B,F]
    {
        int total = SB * (1024 / 4);
        k_transpose<<<(total + 255) / 256, 256>>>((const float4*)inp, (float4*)xT);
    }

    // 2) input projections -> gate-interleaved xg
    {
        dim3 g(G4 / 128, SB / 128);
        k_mma_lin<1><<<g, 256, SMEM_BYTES>>>(xT, Wih_r, xg_r, bih_r, bhh_r, G4);
        k_mma_lin<1><<<g, 256, SMEM_BYTES>>>(xT, Wih_u, xg_u, bih_u, bhh_u, G4);
    }

    // 3) rolling LSTM: 14 sequential FFMA steps, M = 256
    for (int t = 0; t < S_; t++) {
        dim3 g(G4 / 128, B_ / 64);
        const float* hin = (t == 0) ? nullptr : hs + (size_t)(t - 1) * BH;
        const float* cin = (t == 0) ? nullptr : cs + (size_t)(t - 1) * BH;
        k_lstm_step<<<g, 256>>>(hin, Whh_r,
                                xg_r + (size_t)t * B_ * G4, cin,
                                hs + (size_t)t * BH, cs + (size_t)t * BH,
                                (t == 0) ? 1 : 0);
    }

    // 4) init unroll state
    cudaMemcpyAsync(hu0, hs, sizeof(float) * (size_t)SB * 1024, cudaMemcpyDeviceToDevice, 0);
    cudaMemcpyAsync(cu,  cs, sizeof(float) * (size_t)SB * 1024, cudaMemcpyDeviceToDevice, 0);

    // 5) unrolling LSTM: 15 batched tensor-core steps over the active prefix
    for (int j = 0; j <= S_; j++) {
        int nact = (15 - j < 14) ? (15 - j) : 14;
        const float* hin = (j & 1) ? hu1 : hu0;
        float*       ho  = (j & 1) ? hu0 : hu1;
        int final_t = S_ - j;
        dim3 g(G4 / 128, nact * 2);
        k_mma_lstm<<<g, 256, SMEM_BYTES>>>(hin, Whh_u, xg_u, cu, ho, cu, hn, final_t);
    }

    // 6) classifier (rows permuted to [B,S], N-edge)
    {
        dim3 g((C_ + 127) / 128, SB / 128);
        k_mma_lin<0><<<g, 256, SMEM_BYTES>>>(hn, Wc, out, bc, nullptr, C_);
    }
}